// round 8
// baseline (speedup 1.0000x reference)
#include <cuda_runtime.h>
#include <cuda_fp16.h>
#include <cstdint>

// O[n,m] = sum_k softmax(S)[n,k] * V[m,k],  D=256, n=m=8192.
// mma.sync m16n8k16 fp16 (f32 accum). Fragment-major fp16 scratch:
// bulk cp.async stage loads + conflict-free LDS.128 fragment loads.
// PERSISTENT CTAs (grid=148), continuous 3-stage pipeline across tiles.
// 512 threads / 16 warps (4 per SMSP) to keep the tensor pipe covered.
// Warp tile 64x32 (2 x 8 warp grid) on a 128x256 CTA tile.

#define DK 256
#define BM 128
#define BN 256
#define THREADS 512
#define NTILES (32 * 64)
#define GRID_P 148

#define A_BYTES (BM * 64 * 2) /* 16384 */
#define B_BYTES (BN * 64 * 2) /* 32768 */
#define STG_BYTES (A_BYTES + B_BYTES) /* 49152 */
#define SMEM_TOTAL (3 * STG_BYTES)    /* 147456 */

__device__ __half g_Ph[8192 * DK];
__device__ __half g_Vh[8192 * DK];

__device__ __forceinline__ uint32_t smem_u32(const void* p) {
    uint32_t a;
    asm("{ .reg .u64 t; cvta.to.shared.u64 t, %1; cvt.u32.u64 %0, t; }"
        : "=r"(a) : "l"(p));
    return a;
}
__device__ __forceinline__ void cp16(uint32_t dst, const void* src) {
    asm volatile("cp.async.cg.shared.global [%0], [%1], 16;" :: "r"(dst), "l"(src)
                 : "memory");
}
__device__ __forceinline__ void lds128(uint32_t* d, uint32_t addr) {
    asm volatile("ld.shared.v4.b32 {%0,%1,%2,%3}, [%4];"
                 : "=r"(d[0]), "=r"(d[1]), "=r"(d[2]), "=r"(d[3]) : "r"(addr));
}
__device__ __forceinline__ void mma_fp16(float* d, const uint32_t* a,
                                         uint32_t b0, uint32_t b1) {
    asm volatile(
        "mma.sync.aligned.m16n8k16.row.col.f32.f16.f16.f32 "
        "{%0,%1,%2,%3}, {%4,%5,%6,%7}, {%8,%9}, {%0,%1,%2,%3};"
        : "+f"(d[0]), "+f"(d[1]), "+f"(d[2]), "+f"(d[3])
        : "r"(a[0]), "r"(a[1]), "r"(a[2]), "r"(a[3]), "r"(b0), "r"(b1));
}

// Fragment-major index (in fp16 elements) for A scratch, element (r, k):
// [tile128][kc4][wrow2][mt4][ks4][lane32][q4][e2]; q = hk*2 + h8 (a0..a3)
__device__ __forceinline__ size_t idxA(int r, int k) {
    int tile = r >> 7, wrow = (r >> 6) & 1, mt = (r >> 4) & 3;
    int h8 = (r >> 3) & 1, g = r & 7;
    int kc = k >> 6, ks = (k >> 4) & 3, kk = k & 15;
    int hk = kk >> 3, t = (kk >> 1) & 3, e = kk & 1;
    int lane = g * 4 + t;
    int q = hk * 2 + h8;
    return ((((((size_t)tile * 4 + kc) * 2 + wrow) * 4 + mt) * 4 + ks) * 32 + lane) * 8
           + q * 2 + e;
}
// Fragment-major index for B scratch, element (v, k):
// [tile256][kc4][wcol8][j2][ks4][lane32][q4][e2]; q = p*2 + hk (p=(v>>3)&1)
__device__ __forceinline__ size_t idxB(int v, int k) {
    int tile = v >> 8, wcol = (v >> 5) & 7, j = (v >> 4) & 1;
    int p = (v >> 3) & 1, g = v & 7;
    int kc = k >> 6, ks = (k >> 4) & 3, kk = k & 15;
    int hk = kk >> 3, t = (kk >> 1) & 3, e = kk & 1;
    int lane = g * 4 + t;
    int q = p * 2 + hk;
    return ((((((size_t)tile * 4 + kc) * 8 + wcol) * 2 + j) * 4 + ks) * 32 + lane) * 8
           + q * 2 + e;
}

// ------------- fused prologue: softmax (blocks 0..1023) + V cvt ------------
__global__ void prep_k(const float* __restrict__ S, const float* __restrict__ V) {
    if (blockIdx.x < 1024) {
        int row = blockIdx.x * 8 + (threadIdx.x >> 5);
        int lane = threadIdx.x & 31;
        const float4* Sr = reinterpret_cast<const float4*>(S + (size_t)row * DK);
        float4 v0 = Sr[lane * 2];
        float4 v1 = Sr[lane * 2 + 1];
        float e[8] = {v0.x, v0.y, v0.z, v0.w, v1.x, v1.y, v1.z, v1.w};
        float mx = e[0];
#pragma unroll
        for (int i = 1; i < 8; i++) mx = fmaxf(mx, e[i]);
#pragma unroll
        for (int o = 16; o; o >>= 1) mx = fmaxf(mx, __shfl_xor_sync(0xffffffffu, mx, o));
        float s = 0.0f;
#pragma unroll
        for (int i = 0; i < 8; i++) { e[i] = __expf(e[i] - mx); s += e[i]; }
#pragma unroll
        for (int o = 16; o; o >>= 1) s += __shfl_xor_sync(0xffffffffu, s, o);
        float inv = __frcp_rn(s);
#pragma unroll
        for (int t = 0; t < 4; t++) {
            __half2 h = __floats2half2_rn(e[2 * t] * inv, e[2 * t + 1] * inv);
            *reinterpret_cast<__half2*>(&g_Ph[idxA(row, lane * 8 + 2 * t)]) = h;
        }
    } else {
        const float2* V2 = reinterpret_cast<const float2*>(V);
        int base = (blockIdx.x - 1024) * 256 + threadIdx.x;
        const int pairs = 8192 * DK / 2;
#pragma unroll 2
        for (int i = base; i < pairs; i += 512 * 256) {
            float2 f = V2[i];
            int v = i >> 7;
            int k0 = (i << 1) & 255;
            __half2 h = __floats2half2_rn(f.x, f.y);
            *reinterpret_cast<__half2*>(&g_Vh[idxB(v, k0)]) = h;
        }
    }
}

// ---------------- GEMM -----------------------------------------------------
__device__ __forceinline__ void load_stage(uint32_t sb, int s,
                                           const __half* Asrc, const __half* Bsrc,
                                           int kc, int tid) {
    uint32_t base = sb + s * STG_BYTES;
    const __half* Ak = Asrc + (size_t)kc * 8192;  // 16 KB of halves
    const __half* Bk = Bsrc + (size_t)kc * 16384; // 32 KB of halves
#pragma unroll
    for (int it = 0; it < 2; it++) {
        int i = it * THREADS + tid;
        cp16(base + i * 16, Ak + i * 8);
    }
#pragma unroll
    for (int it = 0; it < 4; it++) {
        int i = it * THREADS + tid;
        cp16(base + A_BYTES + i * 16, Bk + i * 8);
    }
    asm volatile("cp.async.commit_group;" ::: "memory");
}

__device__ __forceinline__ void issue_next(uint32_t sb, int& ltile, int& lchunk,
                                           int& gstage, int tid) {
    if (ltile < NTILES) {
        const __half* Asrc = g_Ph + (size_t)(ltile >> 5) * (4 * 8192);
        const __half* Bsrc = g_Vh + (size_t)(ltile & 31) * (4 * 16384);
        load_stage(sb, gstage, Asrc, Bsrc, lchunk, tid);
    } else {
        asm volatile("cp.async.commit_group;" ::: "memory");
    }
    gstage = (gstage == 2) ? 0 : gstage + 1;
    if (++lchunk == 4) { lchunk = 0; ltile += GRID_P; }
}

__global__ void __launch_bounds__(THREADS, 1)
gemm_k(float* __restrict__ out, int m) {
    extern __shared__ __half smh[];
    uint32_t sb = smem_u32(smh);
    int tid = threadIdx.x;
    int lane = tid & 31, warp = tid >> 5;
    int wrow = warp >> 3;  // 0..1 (x64 rows)
    int wcol = warp & 7;   // 0..7 (x32 cols)

    int ltile = blockIdx.x, lchunk = 0, gstage = 0;
    issue_next(sb, ltile, lchunk, gstage, tid);  // chunk 0
    issue_next(sb, ltile, lchunk, gstage, tid);  // chunk 1

    int cstage = 0;
#pragma unroll 1
    for (int tile = blockIdx.x; tile < NTILES; tile += GRID_P) {
        float acc[4][4][4];
#pragma unroll
        for (int i = 0; i < 4; i++)
#pragma unroll
            for (int j = 0; j < 4; j++)
#pragma unroll
                for (int r = 0; r < 4; r++) acc[i][j][r] = 0.0f;

#pragma unroll 1
        for (int k = 0; k < 4; k++) {
            asm volatile("cp.async.wait_group 1;" ::: "memory");
            __syncthreads();
            issue_next(sb, ltile, lchunk, gstage, tid);  // global chunk +2

            uint32_t stage = sb + cstage * STG_BYTES;
            uint32_t aW = stage + (uint32_t)wrow * 8192 + lane * 16;
            uint32_t bW = stage + A_BYTES + (uint32_t)wcol * 4096 + lane * 16;
#pragma unroll
            for (int ks = 0; ks < 4; ks++) {
                uint32_t a[4][4], b[2][4];
#pragma unroll
                for (int mt = 0; mt < 4; mt++)
                    lds128(a[mt], aW + (uint32_t)(mt * 4 + ks) * 512);
#pragma unroll
                for (int j = 0; j < 2; j++)
                    lds128(b[j], bW + (uint32_t)(j * 4 + ks) * 512);
#pragma unroll
                for (int mt = 0; mt < 4; mt++)
#pragma unroll
                    for (int j = 0; j < 2; j++) {
                        mma_fp16(acc[mt][2 * j], a[mt], b[j][0], b[j][1]);
                        mma_fp16(acc[mt][2 * j + 1], a[mt], b[j][2], b[j][3]);
                    }
            }
            cstage = (cstage == 2) ? 0 : cstage + 1;
        }

        // epilogue (regs -> gmem; overlaps next tile's cp.async fill)
        size_t orow0 = (size_t)(tile >> 5) * BM + wrow * 64;
        size_t ocol0 = (size_t)(tile & 31) * BN + wcol * 32;
#pragma unroll
        for (int mt = 0; mt < 4; mt++) {
#pragma unroll
            for (int nt = 0; nt < 4; nt++) {
                size_t r = orow0 + mt * 16 + (lane >> 2);
                size_t c = ocol0 + nt * 8 + (lane & 3) * 2;
                float2 v0 = make_float2(acc[mt][nt][0], acc[mt][nt][1]);
                float2 v1 = make_float2(acc[mt][nt][2], acc[mt][nt][3]);
                *reinterpret_cast<float2*>(out + r * (size_t)m + c) = v0;
                *reinterpret_cast<float2*>(out + (r + 8) * (size_t)m + c) = v1;
            }
        }
    }
}

extern "C" void kernel_launch(void* const* d_in, const int* in_sizes, int n_in,
                              void* d_out, int out_size) {
    const float* S = (const float*)d_in[0];
    const float* V = (const float*)d_in[1];
    float* out = (float*)d_out;
    int m = in_sizes[1] / DK;  // 8192 V rows

    prep_k<<<1536, 256>>>(S, V);

    cudaFuncSetAttribute(gemm_k, cudaFuncAttributeMaxDynamicSharedMemorySize,
                         SMEM_TOTAL);
    gemm_k<<<GRID_P, THREADS, SMEM_TOTAL>>>(out, m);
}

// round 10
// speedup vs baseline: 1.0697x; 1.0697x over previous
#include <cuda_runtime.h>
#include <cuda_fp16.h>
#include <cstdint>
#include <cstring>

// O[n,m] = sum_k softmax(S)[n,k] * V[m,k],  D=256, n=m=8192.
// GEMM (R7 winner, at legacy-mma MAC wall): mma.sync m16n8k16 fp16 f32-acc,
// fragment-major fp16 scratch, persistent CTAs, continuous 3-stage cp.async.
// Prep rewritten: all scratch stores are coalesced 16B st.global.v4.

#define DK 256
#define BM 128
#define BN 256
#define THREADS 256
#define NTILES (32 * 64)
#define GRID_P 148

#define A_BYTES (BM * 64 * 2) /* 16384 */
#define B_BYTES (BN * 64 * 2) /* 32768 */
#define STG_BYTES (A_BYTES + B_BYTES) /* 49152 */
#define SMEM_TOTAL (3 * STG_BYTES)    /* 147456 */

__device__ __half g_Ph[8192 * DK];
__device__ __half g_Vh[8192 * DK];

__device__ __forceinline__ uint32_t h2u(__half2 h) {
    uint32_t u;
    memcpy(&u, &h, 4);
    return u;
}
__device__ __forceinline__ uint32_t smem_u32(const void* p) {
    uint32_t a;
    asm("{ .reg .u64 t; cvta.to.shared.u64 t, %1; cvt.u32.u64 %0, t; }"
        : "=r"(a) : "l"(p));
    return a;
}
__device__ __forceinline__ void cp16(uint32_t dst, const void* src) {
    asm volatile("cp.async.cg.shared.global [%0], [%1], 16;" :: "r"(dst), "l"(src)
                 : "memory");
}
__device__ __forceinline__ void lds128(uint32_t* d, uint32_t addr) {
    asm volatile("ld.shared.v4.b32 {%0,%1,%2,%3}, [%4];"
                 : "=r"(d[0]), "=r"(d[1]), "=r"(d[2]), "=r"(d[3]) : "r"(addr));
}
__device__ __forceinline__ void mma_fp16(float* d, const uint32_t* a,
                                         uint32_t b0, uint32_t b1) {
    asm volatile(
        "mma.sync.aligned.m16n8k16.row.col.f32.f16.f16.f32 "
        "{%0,%1,%2,%3}, {%4,%5,%6,%7}, {%8,%9}, {%0,%1,%2,%3};"
        : "+f"(d[0]), "+f"(d[1]), "+f"(d[2]), "+f"(d[3])
        : "r"(a[0]), "r"(a[1]), "r"(a[2]), "r"(a[3]), "r"(b0), "r"(b1));
}

// Fragment-major index (in fp16 elements) for A scratch, element (r, k):
// [tile128][kc4][wrow2][mt4][ks4][lane32][q4][e2]; q = hk*2 + h8 (a0..a3)
__device__ __forceinline__ size_t idxA(int r, int k) {
    int tile = r >> 7, wrow = (r >> 6) & 1, mt = (r >> 4) & 3;
    int h8 = (r >> 3) & 1, g = r & 7;
    int kc = k >> 6, ks = (k >> 4) & 3, kk = k & 15;
    int hk = kk >> 3, t = (kk >> 1) & 3, e = kk & 1;
    int lane = g * 4 + t;
    int q = hk * 2 + h8;
    return ((((((size_t)tile * 4 + kc) * 2 + wrow) * 4 + mt) * 4 + ks) * 32 + lane) * 8
           + q * 2 + e;
}
// Fragment-major index for B scratch, element (v, k):
// [tile256][kc4][wcol4][j4][ks4][lane32][q4][e2]; q = p*2 + hk (p=(v>>3)&1)
__device__ __forceinline__ size_t idxB(int v, int k) {
    int tile = v >> 8, wcol = (v >> 6) & 3, j = (v >> 4) & 3;
    int p = (v >> 3) & 1, g = v & 7;
    int kc = k >> 6, ks = (k >> 4) & 3, kk = k & 15;
    int hk = kk >> 3, t = (kk >> 1) & 3, e = kk & 1;
    int lane = g * 4 + t;
    int q = p * 2 + hk;
    return ((((((size_t)tile * 4 + kc) * 4 + wcol) * 4 + j) * 4 + ks) * 32 + lane) * 8
           + q * 2 + e;
}

// ---- prep: blocks 0..511 softmax (16 rows each), 512..1023 V convert ------
// All g_Ph / g_Vh stores are 16B coalesced st.global.v4.
#define SROW 264 /* smem row stride in halves: 132 words -> conflict-free */
__global__ void __launch_bounds__(512, 1) prep_k(const float* __restrict__ S,
                                                 const float* __restrict__ V) {
    if (blockIdx.x < 512) {
        __shared__ __half sm[16 * SROW];
        int base = blockIdx.x * 16;
        int w = threadIdx.x >> 5, lane = threadIdx.x & 31;
        // phase 1: warp per row softmax -> smem halves (rows 0..15 of block)
        int row = base + w;
        const float4* Sr = reinterpret_cast<const float4*>(S + (size_t)row * DK);
        float4 v0 = Sr[lane * 2];
        float4 v1 = Sr[lane * 2 + 1];
        float e[8] = {v0.x, v0.y, v0.z, v0.w, v1.x, v1.y, v1.z, v1.w};
        float mx = e[0];
#pragma unroll
        for (int i = 1; i < 8; i++) mx = fmaxf(mx, e[i]);
#pragma unroll
        for (int o = 16; o; o >>= 1) mx = fmaxf(mx, __shfl_xor_sync(0xffffffffu, mx, o));
        float s = 0.0f;
#pragma unroll
        for (int i = 0; i < 8; i++) { e[i] = __expf(e[i] - mx); s += e[i]; }
#pragma unroll
        for (int o = 16; o; o >>= 1) s += __shfl_xor_sync(0xffffffffu, s, o);
        float inv = __frcp_rn(s);
        uint32_t h01 = h2u(__floats2half2_rn(e[0] * inv, e[1] * inv));
        uint32_t h23 = h2u(__floats2half2_rn(e[2] * inv, e[3] * inv));
        uint32_t h45 = h2u(__floats2half2_rn(e[4] * inv, e[5] * inv));
        uint32_t h67 = h2u(__floats2half2_rn(e[6] * inv, e[7] * inv));
        uint32_t sb = smem_u32(sm);
        asm volatile("st.shared.v4.b32 [%0], {%1,%2,%3,%4};"
                     :: "r"(sb + (uint32_t)(w * SROW + lane * 8) * 2),
                        "r"(h01), "r"(h23), "r"(h45), "r"(h67));
        __syncthreads();
        // phase 2: coalesced 16B chunk stores. 512 thr = kc4 x ks4 x lane32.
        // Rows covered by this block: base..base+15 => wrow/mt fixed by base,
        // only (h8=r bit3, g=r bits0..2) vary inside the block.
        int c = threadIdx.x;
        int l = c & 31, ks = (c >> 5) & 3, kc = (c >> 7) & 3;
        int g = l >> 2, t = l & 3;
        int k0 = kc * 64 + ks * 16 + 2 * t;
        const __half2* a0 = reinterpret_cast<const __half2*>(sm + g * SROW);
        const __half2* a8 = reinterpret_cast<const __half2*>(sm + (g + 8) * SROW);
        uint32_t w0 = h2u(a0[k0 >> 1]);        // (g,   k0..k0+1)
        uint32_t w1 = h2u(a8[k0 >> 1]);        // (g+8, k0..k0+1)
        uint32_t w2 = h2u(a0[(k0 >> 1) + 4]);  // (g,   k0+8..k0+9)
        uint32_t w3 = h2u(a8[(k0 >> 1) + 4]);  // (g+8, k0+8..k0+9)
        uint4 outv = make_uint4(w0, w1, w2, w3);
        *reinterpret_cast<uint4*>(&g_Ph[idxA(base + g, k0)]) = outv;
    } else {
        // V convert: one 16B chunk per thread. 262144 chunks total.
        int c = (blockIdx.x - 512) * 512 + threadIdx.x;
        int l = c & 31, ks = (c >> 5) & 3, j = (c >> 7) & 3;
        int wcol = (c >> 9) & 3, kc = (c >> 11) & 3, tile = c >> 13;
        int g = l >> 2, t = l & 3;
        int v0 = tile * 256 + wcol * 64 + j * 16 + g;
        int k0 = kc * 64 + ks * 16 + 2 * t;
        const float2* Va = reinterpret_cast<const float2*>(V + (size_t)v0 * DK);
        const float2* Vb = reinterpret_cast<const float2*>(V + (size_t)(v0 + 8) * DK);
        float2 f0 = Va[k0 >> 1];
        float2 f1 = Va[(k0 >> 1) + 4];
        float2 f2 = Vb[k0 >> 1];
        float2 f3 = Vb[(k0 >> 1) + 4];
        uint4 outv = make_uint4(h2u(__floats2half2_rn(f0.x, f0.y)),
                                h2u(__floats2half2_rn(f2.x, f2.y)),
                                h2u(__floats2half2_rn(f1.x, f1.y)),
                                h2u(__floats2half2_rn(f3.x, f3.y)));
        // chunk layout at idxB(v0,k0): [q0=(p0,hk0)=(g,k0) pair? — match idxB:
        // q = p*2 + hk with e fast: q0=(p=0,hk=0)->(v0,k0), q1=(p=0,hk=1)->(v0,k0+8),
        // q2=(p=1,hk=0)->(v0+8,k0), q3=(p=1,hk=1)->(v0+8,k0+8)
        outv = make_uint4(h2u(__floats2half2_rn(f0.x, f0.y)),   // (v0,  k0)
                          h2u(__floats2half2_rn(f1.x, f1.y)),   // (v0,  k0+8)
                          h2u(__floats2half2_rn(f2.x, f2.y)),   // (v0+8,k0)
                          h2u(__floats2half2_rn(f3.x, f3.y)));  // (v0+8,k0+8)
        *reinterpret_cast<uint4*>(&g_Vh[idxB(v0, k0)]) = outv;
    }
}

// ---------------- GEMM (R7 winner, unchanged) -------------------------------
__device__ __forceinline__ void load_stage(uint32_t sb, int s,
                                           const __half* Asrc, const __half* Bsrc,
                                           int kc, int tid) {
    uint32_t base = sb + s * STG_BYTES;
    const __half* Ak = Asrc + (size_t)kc * 8192;  // 16 KB of halves
    const __half* Bk = Bsrc + (size_t)kc * 16384; // 32 KB of halves
#pragma unroll
    for (int it = 0; it < 4; it++) {
        int i = it * THREADS + tid;
        cp16(base + i * 16, Ak + i * 8);
    }
#pragma unroll
    for (int it = 0; it < 8; it++) {
        int i = it * THREADS + tid;
        cp16(base + A_BYTES + i * 16, Bk + i * 8);
    }
    asm volatile("cp.async.commit_group;" ::: "memory");
}

__device__ __forceinline__ void issue_next(uint32_t sb, int& ltile, int& lchunk,
                                           int& gstage, int tid) {
    if (ltile < NTILES) {
        const __half* Asrc = g_Ph + (size_t)(ltile >> 5) * (4 * 8192);
        const __half* Bsrc = g_Vh + (size_t)(ltile & 31) * (4 * 16384);
        load_stage(sb, gstage, Asrc, Bsrc, lchunk, tid);
    } else {
        asm volatile("cp.async.commit_group;" ::: "memory");
    }
    gstage = (gstage == 2) ? 0 : gstage + 1;
    if (++lchunk == 4) { lchunk = 0; ltile += GRID_P; }
}

__global__ void __launch_bounds__(THREADS, 1)
gemm_k(float* __restrict__ out, int m) {
    extern __shared__ __half smh[];
    uint32_t sb = smem_u32(smh);
    int tid = threadIdx.x;
    int lane = tid & 31, warp = tid >> 5;
    int wrow = warp >> 2;  // 0..1 (x64 rows)
    int wcol = warp & 3;   // 0..3 (x64 cols)

    int ltile = blockIdx.x, lchunk = 0, gstage = 0;
    issue_next(sb, ltile, lchunk, gstage, tid);  // chunk 0
    issue_next(sb, ltile, lchunk, gstage, tid);  // chunk 1

    int cstage = 0;
#pragma unroll 1
    for (int tile = blockIdx.x; tile < NTILES; tile += GRID_P) {
        float acc[4][8][4];
#pragma unroll
        for (int i = 0; i < 4; i++)
#pragma unroll
            for (int j = 0; j < 8; j++)
#pragma unroll
                for (int r = 0; r < 4; r++) acc[i][j][r] = 0.0f;

#pragma unroll 1
        for (int k = 0; k < 4; k++) {
            asm volatile("cp.async.wait_group 1;" ::: "memory");
            __syncthreads();
            issue_next(sb, ltile, lchunk, gstage, tid);  // global chunk +2

            uint32_t stage = sb + cstage * STG_BYTES;
            uint32_t aW = stage + (uint32_t)wrow * 8192 + lane * 16;
            uint32_t bW = stage + A_BYTES + (uint32_t)wcol * 8192 + lane * 16;
#pragma unroll
            for (int ks = 0; ks < 4; ks++) {
                uint32_t a[4][4], b[4][4];
#pragma unroll
                for (int mt = 0; mt < 4; mt++)
                    lds128(a[mt], aW + (uint32_t)(mt * 4 + ks) * 512);
#pragma unroll
                for (int j = 0; j < 4; j++)
                    lds128(b[j], bW + (uint32_t)(j * 4 + ks) * 512);
#pragma unroll
                for (int mt = 0; mt < 4; mt++)
#pragma unroll
                    for (int j = 0; j < 4; j++) {
                        mma_fp16(acc[mt][2 * j], a[mt], b[j][0], b[j][1]);
                        mma_fp16(acc[mt][2 * j + 1], a[mt], b[j][2], b[j][3]);
                    }
            }
            cstage = (cstage == 2) ? 0 : cstage + 1;
        }

        // epilogue (regs -> gmem; overlaps next tile's cp.async fill)
        size_t orow0 = (size_t)(tile >> 5) * BM + wrow * 64;
        size_t ocol0 = (size_t)(tile & 31) * BN + wcol * 64;
#pragma unroll
        for (int mt = 0; mt < 4; mt++) {
#pragma unroll
            for (int nt = 0; nt < 8; nt++) {
                size_t r = orow0 + mt * 16 + (lane >> 2);
                size_t c = ocol0 + nt * 8 + (lane & 3) * 2;
                float2 v0 = make_float2(acc[mt][nt][0], acc[mt][nt][1]);
                float2 v1 = make_float2(acc[mt][nt][2], acc[mt][nt][3]);
                *reinterpret_cast<float2*>(out + r * (size_t)m + c) = v0;
                *reinterpret_cast<float2*>(out + (r + 8) * (size_t)m + c) = v1;
            }
        }
    }
}

extern "C" void kernel_launch(void* const* d_in, const int* in_sizes, int n_in,
                              void* d_out, int out_size) {
    const float* S = (const float*)d_in[0];
    const float* V = (const float*)d_in[1];
    float* out = (float*)d_out;
    int m = in_sizes[1] / DK;  // 8192 V rows

    prep_k<<<1024, 512>>>(S, V);

    cudaFuncSetAttribute(gemm_k, cudaFuncAttributeMaxDynamicSharedMemorySize,
                         SMEM_TOTAL);
    gemm_k<<<GRID_P, THREADS, SMEM_TOTAL>>>(out, m);
}